// round 8
// baseline (speedup 1.0000x reference)
#include <cuda_runtime.h>

// Bilinear resample: B=16, S=128, C=128, fp32.
// R8: R6's proven warp=pixel-pair body (8 independent coalesced 512B
// gathers) with a single-full-wave launch: 1184 CTAs (148 SMs x 8 resident),
// each warp handles 14 consecutive pairs (guarded). __launch_bounds__(256,8)
// pins the register budget so residency cannot silently drop (R7's failure).

#define S 128
#define C 128
#define C4 (C / 4)                 // float4s per pixel
#define NPIX (16 * S * S)          // 262144
#define NPAIR (NPIX / 2)           // 131072
#define WARPS_PER_CTA 8            // 256 threads
#define NBLOCKS 1184               // one full wave at 8 CTAs/SM
#define PAIRS_PER_WARP 14          // 1184*8*14 = 132608 >= NPAIR

__device__ __forceinline__ float4 lerp4(float4 v00, float4 v01, float4 v10,
                                        float4 v11, float fx, float fy)
{
    float4 t, bo, o;
    t.x  = v00.x + (v01.x - v00.x) * fx;
    t.y  = v00.y + (v01.y - v00.y) * fx;
    t.z  = v00.z + (v01.z - v00.z) * fx;
    t.w  = v00.w + (v01.w - v00.w) * fx;
    bo.x = v10.x + (v11.x - v10.x) * fx;
    bo.y = v10.y + (v11.y - v10.y) * fx;
    bo.z = v10.z + (v11.z - v10.z) * fx;
    bo.w = v10.w + (v11.w - v10.w) * fx;
    o.x  = t.x + (bo.x - t.x) * fy;
    o.y  = t.y + (bo.y - t.y) * fy;
    o.z  = t.z + (bo.z - t.z) * fy;
    o.w  = t.w + (bo.w - t.w) * fy;
    return o;
}

__global__ __launch_bounds__(256, 8) void resample_kernel(
    const float* __restrict__ offsets,
    const float* __restrict__ inputs,
    float* __restrict__ out)
{
    const int lane = threadIdx.x & 31;
    const int w = blockIdx.x * WARPS_PER_CTA + (threadIdx.x >> 5);
    const int pbase = w * PAIRS_PER_WARP;

    const float4* off4 = reinterpret_cast<const float4*>(offsets);
    const float4* in4  = reinterpret_cast<const float4*>(inputs);
    float4*       out4 = reinterpret_cast<float4*>(out);

#pragma unroll 1
    for (int k = 0; k < PAIRS_PER_WARP; k++) {
        const int p = pbase + k;
        if (p >= NPAIR) break;

        const int pix0 = p * 2;
        const int jA = pix0 & (S - 1);
        const int i  = (pix0 >> 7) & (S - 1);
        const int b  = pix0 >> 14;
        const float4* base = in4 + (size_t)b * (S * S * C4);
        const float fi = (float)i;

        // 16B broadcast load; consecutive pairs share 128B lines -> L1 hits.
        const float4 off2 = __ldg(off4 + p);

        // Reference semantics: clip [0, S-1], rb = ceil.
        const float yA = fminf(fmaxf(off2.x + fi,              0.0f), (float)(S - 1));
        const float xA = fminf(fmaxf(off2.y + (float)jA,       0.0f), (float)(S - 1));
        const float yB = fminf(fmaxf(off2.z + fi,              0.0f), (float)(S - 1));
        const float xB = fminf(fmaxf(off2.w + (float)(jA + 1), 0.0f), (float)(S - 1));

        const float ay0f = floorf(yA), ax0f = floorf(xA);
        const float by0f = floorf(yB), bx0f = floorf(xB);
        const int aY0 = (int)ay0f,      aX0 = (int)ax0f;
        const int aY1 = (int)ceilf(yA), aX1 = (int)ceilf(xA);
        const int bY0 = (int)by0f,      bX0 = (int)bx0f;
        const int bY1 = (int)ceilf(yB), bX1 = (int)ceilf(xB);
        const float afy = yA - ay0f, afx = xA - ax0f;
        const float bfy = yB - by0f, bfx = xB - bx0f;

        // 8 independent coalesced 512B gathers.
        const float4 a00 = __ldg(base + (aY0 * S + aX0) * C4 + lane);
        const float4 a01 = __ldg(base + (aY0 * S + aX1) * C4 + lane);
        const float4 a10 = __ldg(base + (aY1 * S + aX0) * C4 + lane);
        const float4 a11 = __ldg(base + (aY1 * S + aX1) * C4 + lane);
        const float4 b00 = __ldg(base + (bY0 * S + bX0) * C4 + lane);
        const float4 b01 = __ldg(base + (bY0 * S + bX1) * C4 + lane);
        const float4 b10 = __ldg(base + (bY1 * S + bX0) * C4 + lane);
        const float4 b11 = __ldg(base + (bY1 * S + bX1) * C4 + lane);

        float4* outp = out4 + (size_t)pix0 * C4 + lane;
        outp[0]  = lerp4(a00, a01, a10, a11, afx, afy);
        outp[C4] = lerp4(b00, b01, b10, b11, bfx, bfy);
    }
}

extern "C" void kernel_launch(void* const* d_in, const int* in_sizes, int n_in,
                              void* d_out, int out_size)
{
    const float* offsets = (const float*)d_in[0];
    const float* inputs  = (const float*)d_in[1];
    float* out = (float*)d_out;

    resample_kernel<<<NBLOCKS, WARPS_PER_CTA * 32>>>(offsets, inputs, out);
}

// round 9
// speedup vs baseline: 1.5573x; 1.5573x over previous
#include <cuda_runtime.h>

// Bilinear resample: B=16, S=128, C=128, fp32.
// R9: R6's proven 32-reg warp=pixel-pair body + one-full-wave launch
// (1184 CTAs) with a WARP-GRANULARITY GRID-STRIDE loop. At each step the
// machine's concurrent front is a contiguous band of 9472 pairs (~148 image
// rows, ~9.3MB input) -> L2 holds the band, cross-row corner reuse hits,
// DRAM traffic stays at the compulsory ~240MB (R8 destroyed this with
// long per-warp contiguous chunks -> 394MB).

#define S 128
#define C 128
#define C4 (C / 4)                 // float4s per pixel
#define NPIX (16 * S * S)          // 262144
#define NPAIR (NPIX / 2)           // 131072
#define WARPS_PER_CTA 8            // 256 threads
#define NBLOCKS 1184               // one full wave at 8 CTAs/SM
#define NWARPS (NBLOCKS * WARPS_PER_CTA)   // 9472

__device__ __forceinline__ float4 lerp4(float4 v00, float4 v01, float4 v10,
                                        float4 v11, float fx, float fy)
{
    float4 t, bo, o;
    t.x  = v00.x + (v01.x - v00.x) * fx;
    t.y  = v00.y + (v01.y - v00.y) * fx;
    t.z  = v00.z + (v01.z - v00.z) * fx;
    t.w  = v00.w + (v01.w - v00.w) * fx;
    bo.x = v10.x + (v11.x - v10.x) * fx;
    bo.y = v10.y + (v11.y - v10.y) * fx;
    bo.z = v10.z + (v11.z - v10.z) * fx;
    bo.w = v10.w + (v11.w - v10.w) * fx;
    o.x  = t.x + (bo.x - t.x) * fy;
    o.y  = t.y + (bo.y - t.y) * fy;
    o.z  = t.z + (bo.z - t.z) * fy;
    o.w  = t.w + (bo.w - t.w) * fy;
    return o;
}

__global__ __launch_bounds__(256, 8) void resample_kernel(
    const float* __restrict__ offsets,
    const float* __restrict__ inputs,
    float* __restrict__ out)
{
    const int lane = threadIdx.x & 31;
    const int gw = blockIdx.x * WARPS_PER_CTA + (threadIdx.x >> 5);

    const float4* off4 = reinterpret_cast<const float4*>(offsets);
    const float4* in4  = reinterpret_cast<const float4*>(inputs);
    float4*       out4 = reinterpret_cast<float4*>(out);

#pragma unroll 1
    for (int p = gw; p < NPAIR; p += NWARPS) {
        const int pix0 = p * 2;
        const int jA = pix0 & (S - 1);
        const int i  = (pix0 >> 7) & (S - 1);
        const int b  = pix0 >> 14;
        const float4* base = in4 + (size_t)b * (S * S * C4);
        const float fi = (float)i;

        // 16B broadcast load of both pixels' (dy,dx).
        const float4 off2 = __ldg(off4 + p);

        // Reference semantics: clip [0, S-1], rb = ceil.
        const float yA = fminf(fmaxf(off2.x + fi,              0.0f), (float)(S - 1));
        const float xA = fminf(fmaxf(off2.y + (float)jA,       0.0f), (float)(S - 1));
        const float yB = fminf(fmaxf(off2.z + fi,              0.0f), (float)(S - 1));
        const float xB = fminf(fmaxf(off2.w + (float)(jA + 1), 0.0f), (float)(S - 1));

        const float ay0f = floorf(yA), ax0f = floorf(xA);
        const float by0f = floorf(yB), bx0f = floorf(xB);
        const int aY0 = (int)ay0f,      aX0 = (int)ax0f;
        const int aY1 = (int)ceilf(yA), aX1 = (int)ceilf(xA);
        const int bY0 = (int)by0f,      bX0 = (int)bx0f;
        const int bY1 = (int)ceilf(yB), bX1 = (int)ceilf(xB);
        const float afy = yA - ay0f, afx = xA - ax0f;
        const float bfy = yB - by0f, bfx = xB - bx0f;

        // 8 independent coalesced 512B gathers.
        const float4 a00 = __ldg(base + (aY0 * S + aX0) * C4 + lane);
        const float4 a01 = __ldg(base + (aY0 * S + aX1) * C4 + lane);
        const float4 a10 = __ldg(base + (aY1 * S + aX0) * C4 + lane);
        const float4 a11 = __ldg(base + (aY1 * S + aX1) * C4 + lane);
        const float4 b00 = __ldg(base + (bY0 * S + bX0) * C4 + lane);
        const float4 b01 = __ldg(base + (bY0 * S + bX1) * C4 + lane);
        const float4 b10 = __ldg(base + (bY1 * S + bX0) * C4 + lane);
        const float4 b11 = __ldg(base + (bY1 * S + bX1) * C4 + lane);

        float4* outp = out4 + (size_t)pix0 * C4 + lane;
        outp[0]  = lerp4(a00, a01, a10, a11, afx, afy);
        outp[C4] = lerp4(b00, b01, b10, b11, bfx, bfy);
    }
}

extern "C" void kernel_launch(void* const* d_in, const int* in_sizes, int n_in,
                              void* d_out, int out_size)
{
    const float* offsets = (const float*)d_in[0];
    const float* inputs  = (const float*)d_in[1];
    float* out = (float*)d_out;

    resample_kernel<<<NBLOCKS, WARPS_PER_CTA * 32>>>(offsets, inputs, out);
}

// round 10
// speedup vs baseline: 1.6052x; 1.0307x over previous
#include <cuda_runtime.h>

// Bilinear resample: B=16, S=128, C=128, fp32.
// R10: R9 (one-wave grid-stride, band-local schedule, 32-reg pair body)
// + software-pipelined OFFSETS load. Under grid-stride, each iteration's
// offsets load jumps 150KB (never L1-hit), creating a second serial memory
// epoch per iteration. Prefetching iteration k+1's 16B offsets at the top
// of iteration k overlaps it with the gathers, leaving one exposed epoch.

#define S 128
#define C 128
#define C4 (C / 4)                 // float4s per pixel
#define NPIX (16 * S * S)          // 262144
#define NPAIR (NPIX / 2)           // 131072
#define WARPS_PER_CTA 8            // 256 threads
#define NBLOCKS 1184               // one full wave at 8 CTAs/SM
#define NWARPS (NBLOCKS * WARPS_PER_CTA)   // 9472

__device__ __forceinline__ float4 lerp4(float4 v00, float4 v01, float4 v10,
                                        float4 v11, float fx, float fy)
{
    float4 t, bo, o;
    t.x  = v00.x + (v01.x - v00.x) * fx;
    t.y  = v00.y + (v01.y - v00.y) * fx;
    t.z  = v00.z + (v01.z - v00.z) * fx;
    t.w  = v00.w + (v01.w - v00.w) * fx;
    bo.x = v10.x + (v11.x - v10.x) * fx;
    bo.y = v10.y + (v11.y - v10.y) * fx;
    bo.z = v10.z + (v11.z - v10.z) * fx;
    bo.w = v10.w + (v11.w - v10.w) * fx;
    o.x  = t.x + (bo.x - t.x) * fy;
    o.y  = t.y + (bo.y - t.y) * fy;
    o.z  = t.z + (bo.z - t.z) * fy;
    o.w  = t.w + (bo.w - t.w) * fy;
    return o;
}

__global__ __launch_bounds__(256, 7) void resample_kernel(
    const float* __restrict__ offsets,
    const float* __restrict__ inputs,
    float* __restrict__ out)
{
    const int lane = threadIdx.x & 31;
    const int gw = blockIdx.x * WARPS_PER_CTA + (threadIdx.x >> 5);

    const float4* off4 = reinterpret_cast<const float4*>(offsets);
    const float4* in4  = reinterpret_cast<const float4*>(inputs);
    float4*       out4 = reinterpret_cast<float4*>(out);

    // Prologue: load first iteration's offsets.
    float4 off_next = (gw < NPAIR) ? __ldg(off4 + gw)
                                   : make_float4(0.f, 0.f, 0.f, 0.f);

#pragma unroll 1
    for (int p = gw; p < NPAIR; p += NWARPS) {
        const float4 off2 = off_next;
        // Issue next iteration's offsets load NOW; it completes while this
        // iteration's gathers are in flight.
        const int pn = p + NWARPS;
        if (pn < NPAIR) off_next = __ldg(off4 + pn);

        const int pix0 = p * 2;
        const int jA = pix0 & (S - 1);
        const int i  = (pix0 >> 7) & (S - 1);
        const int b  = pix0 >> 14;
        const float4* base = in4 + (size_t)b * (S * S * C4);
        const float fi = (float)i;

        // Reference semantics: clip [0, S-1], rb = ceil.
        const float yA = fminf(fmaxf(off2.x + fi,              0.0f), (float)(S - 1));
        const float xA = fminf(fmaxf(off2.y + (float)jA,       0.0f), (float)(S - 1));
        const float yB = fminf(fmaxf(off2.z + fi,              0.0f), (float)(S - 1));
        const float xB = fminf(fmaxf(off2.w + (float)(jA + 1), 0.0f), (float)(S - 1));

        const float ay0f = floorf(yA), ax0f = floorf(xA);
        const float by0f = floorf(yB), bx0f = floorf(xB);
        const int aY0 = (int)ay0f,      aX0 = (int)ax0f;
        const int aY1 = (int)ceilf(yA), aX1 = (int)ceilf(xA);
        const int bY0 = (int)by0f,      bX0 = (int)bx0f;
        const int bY1 = (int)ceilf(yB), bX1 = (int)ceilf(xB);
        const float afy = yA - ay0f, afx = xA - ax0f;
        const float bfy = yB - by0f, bfx = xB - bx0f;

        // 8 independent coalesced 512B gathers.
        const float4 a00 = __ldg(base + (aY0 * S + aX0) * C4 + lane);
        const float4 a01 = __ldg(base + (aY0 * S + aX1) * C4 + lane);
        const float4 a10 = __ldg(base + (aY1 * S + aX0) * C4 + lane);
        const float4 a11 = __ldg(base + (aY1 * S + aX1) * C4 + lane);
        const float4 b00 = __ldg(base + (bY0 * S + bX0) * C4 + lane);
        const float4 b01 = __ldg(base + (bY0 * S + bX1) * C4 + lane);
        const float4 b10 = __ldg(base + (bY1 * S + bX0) * C4 + lane);
        const float4 b11 = __ldg(base + (bY1 * S + bX1) * C4 + lane);

        float4* outp = out4 + (size_t)pix0 * C4 + lane;
        outp[0]  = lerp4(a00, a01, a10, a11, afx, afy);
        outp[C4] = lerp4(b00, b01, b10, b11, bfx, bfy);
    }
}

extern "C" void kernel_launch(void* const* d_in, const int* in_sizes, int n_in,
                              void* d_out, int out_size)
{
    const float* offsets = (const float*)d_in[0];
    const float* inputs  = (const float*)d_in[1];
    float* out = (float*)d_out;

    resample_kernel<<<NBLOCKS, WARPS_PER_CTA * 32>>>(offsets, inputs, out);
}